// round 10
// baseline (speedup 1.0000x reference)
#include <cuda_runtime.h>
#include <cuda_fp16.h>

#define EMBED 128
#define ATTR 25
#define REM 28
#define NLEVEL 50
#define NCOMB 240                    // 2*2*3*20
#define NFULL (NLEVEL * NCOMB)       // 12000 full-product rows

#define WPAD 129                     // padded pitch: conflict-free dot reads
#define F_TMP (EMBED * WPAD)         // 16512 floats, W region
#define BUILD_SMEM_BYTES ((F_TMP + 77 * EMBED) * 4)   // 66048 + 39424 = 105472

// Full product table, fp16: 12000 * 128 * 2 B = 3 MB (L2-resident)
__device__ __half g_Full[NFULL * EMBED];

// ---- Prologue: one kernel, 152 blocks. Each block stages W, recomputes the 77
// projected temp rows, and writes its slice of the fp16 full-product table.
__global__ void __launch_bounds__(256)
build_kernel(const float* __restrict__ level_tab,
             const float* __restrict__ type_tab,
             const float* __restrict__ feature_tab,
             const float* __restrict__ exchange_tab,
             const float* __restrict__ pair_tab,
             const float* __restrict__ W,
             const float* __restrict__ b)
{
    extern __shared__ float sm[];
    float* sW   = sm;            // sW[e*WPAD + k] = W[e][k]
    float* sTmp = sm + F_TMP;    // 77 projected rows, fp32

    const int tid = threadIdx.x;

    // Stage W: coalesced, 4096 float4 over 256 threads (16 each).
    {
        const float4* W4 = reinterpret_cast<const float4*>(W);
        #pragma unroll 4
        for (int i = tid; i < EMBED * EMBED / 4; i += 256) {
            float4 v = W4[i];
            int e = i >> 5, k = (i & 31) << 2;
            float* dst = sW + e * WPAD + k;
            dst[0] = v.x; dst[1] = v.y; dst[2] = v.z; dst[3] = v.w;
        }
    }
    __syncthreads();

    // 77 projected rows: 0-49 level, 50-51 type, 52-53 feature, 54-56 exchange,
    // 57-76 pair (+b folded). Lanes span e -> sW reads conflict-free, tab reads broadcast.
    for (int item = tid; item < 77 * EMBED; item += 256) {
        int r = item >> 7, e = item & 127;
        const float* we = sW + e * WPAD;
        const float* tab; int off, dim; float s = 0.0f;
        if (r < 50)      { tab = level_tab    + r * ATTR;        off = 0;   dim = ATTR; }
        else if (r < 52) { tab = type_tab     + (r - 50) * ATTR; off = 25;  dim = ATTR; }
        else if (r < 54) { tab = feature_tab  + (r - 52) * ATTR; off = 50;  dim = ATTR; }
        else if (r < 57) { tab = exchange_tab + (r - 54) * ATTR; off = 75;  dim = ATTR; }
        else             { tab = pair_tab     + (r - 57) * REM;  off = 100; dim = REM; s = b[e]; }
        #pragma unroll 5
        for (int k = 0; k < dim; k++)
            s += tab[k] * we[off + k];
        sTmp[r * EMBED + e] = s;
    }
    __syncthreads();

    // Write this block's slice of the full-product table (grid-stride over half2 items).
    const float2* tmp2 = reinterpret_cast<const float2*>(sTmp);   // [row77*64 + j]
    __half2* full2 = reinterpret_cast<__half2*>(g_Full);
    const int total = NFULL * (EMBED / 2);                        // 768000
    for (int i = blockIdx.x * 256 + tid; i < total; i += gridDim.x * 256) {
        int row = i >> 6;           // full row index
        int j   = i & 63;           // float2 position within row
        int l = row / NCOMB;
        int c = row - l * NCOMB;
        int p = c % 20, x = (c / 20) % 3, f = (c / 60) % 2, t = c / 120;
        float2 a  = tmp2[l * 64 + j];
        float2 v1 = tmp2[(50 + t) * 64 + j];
        float2 v2 = tmp2[(52 + f) * 64 + j];
        float2 v3 = tmp2[(54 + x) * 64 + j];
        float2 v4 = tmp2[(57 + p) * 64 + j];
        float s0 = a.x + v1.x + v2.x + v3.x + v4.x;
        float s1 = a.y + v1.y + v2.y + v3.y + v4.y;
        full2[i] = __floats2half2_rn(s0, s1);
    }
}

// ---- Gather: pure streaming (unchanged — at DRAM-write floor ~86us).
__global__ void __launch_bounds__(256, 6)
gather_kernel(const int* __restrict__ level_idx,
              const int* __restrict__ type_idx,
              const int* __restrict__ feature_idx,
              const int* __restrict__ exchange_idx,
              const int* __restrict__ pair_idx,
              float4* __restrict__ out, int n)
{
    const uint2* full2 = reinterpret_cast<const uint2*>(g_Full);
    const int lane   = threadIdx.x & 31;
    const int warp   = (blockIdx.x * 256 + threadIdx.x) >> 5;
    const int nwarps = (gridDim.x * 256) >> 5;

    int r = warp * 8;
    const int stride = nwarps * 8;

    for (; r + 7 < n; r += stride) {
        int4 L0 = *reinterpret_cast<const int4*>(level_idx + r);
        int4 L1 = *reinterpret_cast<const int4*>(level_idx + r + 4);
        int4 T0 = *reinterpret_cast<const int4*>(type_idx + r);
        int4 T1 = *reinterpret_cast<const int4*>(type_idx + r + 4);
        int4 F0 = *reinterpret_cast<const int4*>(feature_idx + r);
        int4 F1 = *reinterpret_cast<const int4*>(feature_idx + r + 4);
        int4 X0 = *reinterpret_cast<const int4*>(exchange_idx + r);
        int4 X1 = *reinterpret_cast<const int4*>(exchange_idx + r + 4);
        int4 P0 = *reinterpret_cast<const int4*>(pair_idx + r);
        int4 P1 = *reinterpret_cast<const int4*>(pair_idx + r + 4);

        int l[8] = {L0.x, L0.y, L0.z, L0.w, L1.x, L1.y, L1.z, L1.w};
        int t[8] = {T0.x, T0.y, T0.z, T0.w, T1.x, T1.y, T1.z, T1.w};
        int f[8] = {F0.x, F0.y, F0.z, F0.w, F1.x, F1.y, F1.z, F1.w};
        int x[8] = {X0.x, X0.y, X0.z, X0.w, X1.x, X1.y, X1.z, X1.w};
        int p[8] = {P0.x, P0.y, P0.z, P0.w, P1.x, P1.y, P1.z, P1.w};

        uint2 hv[8];
        #pragma unroll
        for (int k = 0; k < 8; k++) {
            int row = l[k] * NCOMB + ((t[k] * 2 + f[k]) * 3 + x[k]) * 20 + p[k];
            hv[k] = __ldg(&full2[row * 32 + lane]);
        }
        #pragma unroll
        for (int k = 0; k < 8; k++) {
            const __half2* hp = reinterpret_cast<const __half2*>(&hv[k]);
            float2 f0 = __half22float2(hp[0]);
            float2 f1 = __half22float2(hp[1]);
            float4 s;
            s.x = f0.x; s.y = f0.y; s.z = f1.x; s.w = f1.y;
            __stcs(out + (size_t)(r + k) * 32 + lane, s);
        }
    }
    for (; r < n; r++) {   // tail
        int row = level_idx[r] * NCOMB
                + ((type_idx[r] * 2 + feature_idx[r]) * 3 + exchange_idx[r]) * 20
                + pair_idx[r];
        uint2 hv = __ldg(&full2[row * 32 + lane]);
        const __half2* hp = reinterpret_cast<const __half2*>(&hv);
        float2 f0 = __half22float2(hp[0]);
        float2 f1 = __half22float2(hp[1]);
        float4 s;
        s.x = f0.x; s.y = f0.y; s.z = f1.x; s.w = f1.y;
        out[(size_t)r * 32 + lane] = s;
    }
}

extern "C" void kernel_launch(void* const* d_in, const int* in_sizes, int n_in,
                              void* d_out, int out_size) {
    const float* level_tab    = (const float*)d_in[0];
    const float* type_tab     = (const float*)d_in[1];
    const float* feature_tab  = (const float*)d_in[2];
    const float* exchange_tab = (const float*)d_in[3];
    const float* pair_tab     = (const float*)d_in[4];
    const float* W            = (const float*)d_in[5];
    const float* b            = (const float*)d_in[6];
    const int* level_idx      = (const int*)d_in[7];
    const int* type_idx       = (const int*)d_in[8];
    const int* feature_idx    = (const int*)d_in[9];
    const int* exchange_idx   = (const int*)d_in[10];
    const int* pair_idx       = (const int*)d_in[11];

    int n = in_sizes[7];   // N rows

    int sm_count = 148;
    cudaDeviceGetAttribute(&sm_count, cudaDevAttrMultiProcessorCount, 0);

    cudaFuncSetAttribute(build_kernel,
                         cudaFuncAttributeMaxDynamicSharedMemorySize, BUILD_SMEM_BYTES);

    // One parallel prologue: every block self-builds tables, writes its table slice.
    build_kernel<<<sm_count, 256, BUILD_SMEM_BYTES>>>(
        level_tab, type_tab, feature_tab, exchange_tab, pair_tab, W, b);

    // 6 blocks/SM x 256 threads = 48 warps/SM, no smem
    gather_kernel<<<6 * sm_count, 256>>>(level_idx, type_idx, feature_idx,
                                         exchange_idx, pair_idx,
                                         (float4*)d_out, n);
}

// round 11
// speedup vs baseline: 1.2189x; 1.2189x over previous
#include <cuda_runtime.h>
#include <cuda_fp16.h>

#define EMBED 128
#define ATTR 25
#define REM 28
#define NLEVEL 50
#define NCOMB 240                    // 2*2*3*20
#define NROWS (NLEVEL + NCOMB)       // 290 base rows
#define NFULL (NLEVEL * NCOMB)       // 12000 full-product rows

// Base projected tables (fp32, exact)
__device__ float g_Lrow[NLEVEL * EMBED];
__device__ float g_Crow[NCOMB * EMBED];
// Full product table, fp16: 12000 * 128 * 2 B = 3 MB (L2-resident)
__device__ __half g_Full[NFULL * EMBED];

// ---- Kernel A: warp per (row, element). Lane k holds term k of the dot;
// W reads coalesced across lanes, table reads broadcast; shfl-reduce. No smem.
__global__ void __launch_bounds__(256)
base_kernel(const float* __restrict__ level_tab,
            const float* __restrict__ type_tab,
            const float* __restrict__ feature_tab,
            const float* __restrict__ exchange_tab,
            const float* __restrict__ pair_tab,
            const float* __restrict__ W,
            const float* __restrict__ b)
{
    const int lane  = threadIdx.x & 31;
    const int wid   = (blockIdx.x * 256 + threadIdx.x) >> 5;
    const int nw    = (gridDim.x * 256) >> 5;
    const int ntask = NROWS * EMBED;      // 37120

    for (int task = wid; task < ntask; task += nw) {
        int r = task >> 7;                // 0..289
        int e = task & 127;
        const float* wrow = W + e * EMBED;
        float acc = 0.0f;

        if (r < NLEVEL) {
            if (lane < ATTR)
                acc = level_tab[r * ATTR + lane] * wrow[lane];
        } else {
            int c = r - NLEVEL;
            int p = c % 20, x = (c / 20) % 3, f = (c / 60) % 2, t = c / 120;
            if (lane < ATTR)
                acc = type_tab[t * ATTR + lane]     * wrow[25 + lane]
                    + feature_tab[f * ATTR + lane]  * wrow[50 + lane]
                    + exchange_tab[x * ATTR + lane] * wrow[75 + lane];
            if (lane < REM)
                acc += pair_tab[p * REM + lane] * wrow[100 + lane];
        }

        #pragma unroll
        for (int o = 16; o > 0; o >>= 1)
            acc += __shfl_xor_sync(0xffffffffu, acc, o);

        if (lane == 0) {
            if (r < NLEVEL) g_Lrow[r * EMBED + e] = acc;
            else            g_Crow[(r - NLEVEL) * EMBED + e] = acc + b[e];
        }
    }
}

// ---- Kernel B: expand to 12000-row fp16 full-product table (fp32 sum, one fp16 round).
__global__ void __launch_bounds__(256)
expand_kernel()
{
    const int total = NFULL * (EMBED / 2);
    __half2* full2 = reinterpret_cast<__half2*>(g_Full);
    for (int i = blockIdx.x * 256 + threadIdx.x; i < total; i += gridDim.x * 256) {
        int row = i >> 6;          // / 64
        int pos = (i & 63) << 1;
        int l = row / NCOMB;
        int c = row - l * NCOMB;
        float s0 = g_Lrow[l * EMBED + pos]     + g_Crow[c * EMBED + pos];
        float s1 = g_Lrow[l * EMBED + pos + 1] + g_Crow[c * EMBED + pos + 1];
        full2[i] = __floats2half2_rn(s0, s1);
    }
}

// ---- Kernel C: pure streaming gather (unchanged — at DRAM-write floor ~86us).
__global__ void __launch_bounds__(256, 6)
gather_kernel(const int* __restrict__ level_idx,
              const int* __restrict__ type_idx,
              const int* __restrict__ feature_idx,
              const int* __restrict__ exchange_idx,
              const int* __restrict__ pair_idx,
              float4* __restrict__ out, int n)
{
    const uint2* full2 = reinterpret_cast<const uint2*>(g_Full);
    const int lane   = threadIdx.x & 31;
    const int warp   = (blockIdx.x * 256 + threadIdx.x) >> 5;
    const int nwarps = (gridDim.x * 256) >> 5;

    int r = warp * 8;
    const int stride = nwarps * 8;

    for (; r + 7 < n; r += stride) {
        int4 L0 = *reinterpret_cast<const int4*>(level_idx + r);
        int4 L1 = *reinterpret_cast<const int4*>(level_idx + r + 4);
        int4 T0 = *reinterpret_cast<const int4*>(type_idx + r);
        int4 T1 = *reinterpret_cast<const int4*>(type_idx + r + 4);
        int4 F0 = *reinterpret_cast<const int4*>(feature_idx + r);
        int4 F1 = *reinterpret_cast<const int4*>(feature_idx + r + 4);
        int4 X0 = *reinterpret_cast<const int4*>(exchange_idx + r);
        int4 X1 = *reinterpret_cast<const int4*>(exchange_idx + r + 4);
        int4 P0 = *reinterpret_cast<const int4*>(pair_idx + r);
        int4 P1 = *reinterpret_cast<const int4*>(pair_idx + r + 4);

        int l[8] = {L0.x, L0.y, L0.z, L0.w, L1.x, L1.y, L1.z, L1.w};
        int t[8] = {T0.x, T0.y, T0.z, T0.w, T1.x, T1.y, T1.z, T1.w};
        int f[8] = {F0.x, F0.y, F0.z, F0.w, F1.x, F1.y, F1.z, F1.w};
        int x[8] = {X0.x, X0.y, X0.z, X0.w, X1.x, X1.y, X1.z, X1.w};
        int p[8] = {P0.x, P0.y, P0.z, P0.w, P1.x, P1.y, P1.z, P1.w};

        uint2 hv[8];
        #pragma unroll
        for (int k = 0; k < 8; k++) {
            int row = l[k] * NCOMB + ((t[k] * 2 + f[k]) * 3 + x[k]) * 20 + p[k];
            hv[k] = __ldg(&full2[row * 32 + lane]);
        }
        #pragma unroll
        for (int k = 0; k < 8; k++) {
            const __half2* hp = reinterpret_cast<const __half2*>(&hv[k]);
            float2 f0 = __half22float2(hp[0]);
            float2 f1 = __half22float2(hp[1]);
            float4 s;
            s.x = f0.x; s.y = f0.y; s.z = f1.x; s.w = f1.y;
            __stcs(out + (size_t)(r + k) * 32 + lane, s);
        }
    }
    for (; r < n; r++) {   // tail
        int row = level_idx[r] * NCOMB
                + ((type_idx[r] * 2 + feature_idx[r]) * 3 + exchange_idx[r]) * 20
                + pair_idx[r];
        uint2 hv = __ldg(&full2[row * 32 + lane]);
        const __half2* hp = reinterpret_cast<const __half2*>(&hv);
        float2 f0 = __half22float2(hp[0]);
        float2 f1 = __half22float2(hp[1]);
        float4 s;
        s.x = f0.x; s.y = f0.y; s.z = f1.x; s.w = f1.y;
        out[(size_t)r * 32 + lane] = s;
    }
}

extern "C" void kernel_launch(void* const* d_in, const int* in_sizes, int n_in,
                              void* d_out, int out_size) {
    const float* level_tab    = (const float*)d_in[0];
    const float* type_tab     = (const float*)d_in[1];
    const float* feature_tab  = (const float*)d_in[2];
    const float* exchange_tab = (const float*)d_in[3];
    const float* pair_tab     = (const float*)d_in[4];
    const float* W            = (const float*)d_in[5];
    const float* b            = (const float*)d_in[6];
    const int* level_idx      = (const int*)d_in[7];
    const int* type_idx       = (const int*)d_in[8];
    const int* feature_idx    = (const int*)d_in[9];
    const int* exchange_idx   = (const int*)d_in[10];
    const int* pair_idx       = (const int*)d_in[11];

    int n = in_sizes[7];   // N rows

    int sm_count = 148;
    cudaDeviceGetAttribute(&sm_count, cudaDevAttrMultiProcessorCount, 0);

    // 4 blocks/SM x 8 warps: 37120 warp-tasks spread over ~4800 warps, no smem.
    base_kernel<<<4 * sm_count, 256>>>(level_tab, type_tab, feature_tab,
                                       exchange_tab, pair_tab, W, b);
    expand_kernel<<<4 * sm_count, 256>>>();

    // 6 blocks/SM x 256 threads = 48 warps/SM, no smem
    gather_kernel<<<6 * sm_count, 256>>>(level_idx, type_idx, feature_idx,
                                         exchange_idx, pair_idx,
                                         (float4*)d_out, n);
}

// round 12
// speedup vs baseline: 1.2574x; 1.0316x over previous
#include <cuda_runtime.h>
#include <cuda_fp16.h>

#define EMBED 128
#define ATTR 25
#define REM 28
#define NLEVEL 50
#define NCOMB 240                    // 2*2*3*20
#define NFULL (NLEVEL * NCOMB)       // 12000 full-product rows

// Base projected tables (fp32, exact)
__device__ float g_Lrow[NLEVEL * EMBED];
__device__ float g_Crow[NCOMB * EMBED];
// Full product table, fp16: 12000 * 128 * 2 B = 3 MB (L2-resident)
__device__ __half g_Full[NFULL * EMBED];

// ---- Kernel A: warp per (e, row-block). Lanes span rows; W[e][k] is a broadcast
// load, table reads are L1-resident. No shuffles, no smem, 1280 independent tasks.
__global__ void __launch_bounds__(256)
base_kernel(const float* __restrict__ level_tab,
            const float* __restrict__ type_tab,
            const float* __restrict__ feature_tab,
            const float* __restrict__ exchange_tab,
            const float* __restrict__ pair_tab,
            const float* __restrict__ W,
            const float* __restrict__ b)
{
    const int lane = threadIdx.x & 31;
    const int wid  = (blockIdx.x * 256 + threadIdx.x) >> 5;
    const int nw   = (gridDim.x * 256) >> 5;

    // Tasks 0..255: level rows.   task = e*2 + rb   (rb: rows rb*32..rb*32+31)
    // Tasks 256..1279: combined.  task-256 = e*8 + cb (cb: c = cb*32+lane)
    const int NTASK = 128 * 2 + 128 * 8;   // 1280

    for (int task = wid; task < NTASK; task += nw) {
        if (task < 256) {
            int e  = task >> 1;
            int r  = ((task & 1) << 5) + lane;
            if (r >= NLEVEL) continue;
            const float* wrow = W + e * EMBED;       // broadcast across lanes
            const float* lt = level_tab + r * ATTR;  // per-lane row, L1-resident
            float s0 = 0.f, s1 = 0.f, s2 = 0.f, s3 = 0.f;
            #pragma unroll
            for (int k = 0; k < 24; k += 4) {
                s0 += lt[k]     * wrow[k];
                s1 += lt[k + 1] * wrow[k + 1];
                s2 += lt[k + 2] * wrow[k + 2];
                s3 += lt[k + 3] * wrow[k + 3];
            }
            s0 += lt[24] * wrow[24];
            g_Lrow[r * EMBED + e] = (s0 + s1) + (s2 + s3);
        } else {
            int tt = task - 256;
            int e  = tt >> 3;
            int c  = ((tt & 7) << 5) + lane;
            if (c >= NCOMB) continue;
            int p = c % 20, x = (c / 20) % 3, f = (c / 60) % 2, t = c / 120;
            const float* wrow = W + e * EMBED;
            const float* ta = type_tab     + t * ATTR;
            const float* fa = feature_tab  + f * ATTR;
            const float* xa = exchange_tab + x * ATTR;
            const float* pa = pair_tab     + p * REM;
            float s0 = b[e], s1 = 0.f, s2 = 0.f, s3 = 0.f;
            #pragma unroll
            for (int k = 0; k < ATTR; k++) {
                s0 += ta[k] * wrow[25 + k];
                s1 += fa[k] * wrow[50 + k];
                s2 += xa[k] * wrow[75 + k];
            }
            #pragma unroll
            for (int k = 0; k < REM; k++)
                s3 += pa[k] * wrow[100 + k];
            g_Crow[c * EMBED + e] = (s0 + s1) + (s2 + s3);
        }
    }
}

// ---- Kernel B: expand to 12000-row fp16 full-product table (fp32 sum, one fp16 round).
__global__ void __launch_bounds__(256)
expand_kernel()
{
    const int total = NFULL * (EMBED / 2);
    __half2* full2 = reinterpret_cast<__half2*>(g_Full);
    for (int i = blockIdx.x * 256 + threadIdx.x; i < total; i += gridDim.x * 256) {
        int row = i >> 6;          // / 64
        int pos = (i & 63) << 1;
        int l = row / NCOMB;
        int c = row - l * NCOMB;
        float s0 = g_Lrow[l * EMBED + pos]     + g_Crow[c * EMBED + pos];
        float s1 = g_Lrow[l * EMBED + pos + 1] + g_Crow[c * EMBED + pos + 1];
        full2[i] = __floats2half2_rn(s0, s1);
    }
}

// ---- Kernel C: pure streaming gather (unchanged — at DRAM-write floor ~87us).
__global__ void __launch_bounds__(256, 6)
gather_kernel(const int* __restrict__ level_idx,
              const int* __restrict__ type_idx,
              const int* __restrict__ feature_idx,
              const int* __restrict__ exchange_idx,
              const int* __restrict__ pair_idx,
              float4* __restrict__ out, int n)
{
    const uint2* full2 = reinterpret_cast<const uint2*>(g_Full);
    const int lane   = threadIdx.x & 31;
    const int warp   = (blockIdx.x * 256 + threadIdx.x) >> 5;
    const int nwarps = (gridDim.x * 256) >> 5;

    int r = warp * 8;
    const int stride = nwarps * 8;

    for (; r + 7 < n; r += stride) {
        int4 L0 = *reinterpret_cast<const int4*>(level_idx + r);
        int4 L1 = *reinterpret_cast<const int4*>(level_idx + r + 4);
        int4 T0 = *reinterpret_cast<const int4*>(type_idx + r);
        int4 T1 = *reinterpret_cast<const int4*>(type_idx + r + 4);
        int4 F0 = *reinterpret_cast<const int4*>(feature_idx + r);
        int4 F1 = *reinterpret_cast<const int4*>(feature_idx + r + 4);
        int4 X0 = *reinterpret_cast<const int4*>(exchange_idx + r);
        int4 X1 = *reinterpret_cast<const int4*>(exchange_idx + r + 4);
        int4 P0 = *reinterpret_cast<const int4*>(pair_idx + r);
        int4 P1 = *reinterpret_cast<const int4*>(pair_idx + r + 4);

        int l[8] = {L0.x, L0.y, L0.z, L0.w, L1.x, L1.y, L1.z, L1.w};
        int t[8] = {T0.x, T0.y, T0.z, T0.w, T1.x, T1.y, T1.z, T1.w};
        int f[8] = {F0.x, F0.y, F0.z, F0.w, F1.x, F1.y, F1.z, F1.w};
        int x[8] = {X0.x, X0.y, X0.z, X0.w, X1.x, X1.y, X1.z, X1.w};
        int p[8] = {P0.x, P0.y, P0.z, P0.w, P1.x, P1.y, P1.z, P1.w};

        uint2 hv[8];
        #pragma unroll
        for (int k = 0; k < 8; k++) {
            int row = l[k] * NCOMB + ((t[k] * 2 + f[k]) * 3 + x[k]) * 20 + p[k];
            hv[k] = __ldg(&full2[row * 32 + lane]);
        }
        #pragma unroll
        for (int k = 0; k < 8; k++) {
            const __half2* hp = reinterpret_cast<const __half2*>(&hv[k]);
            float2 f0 = __half22float2(hp[0]);
            float2 f1 = __half22float2(hp[1]);
            float4 s;
            s.x = f0.x; s.y = f0.y; s.z = f1.x; s.w = f1.y;
            __stcs(out + (size_t)(r + k) * 32 + lane, s);
        }
    }
    for (; r < n; r++) {   // tail
        int row = level_idx[r] * NCOMB
                + ((type_idx[r] * 2 + feature_idx[r]) * 3 + exchange_idx[r]) * 20
                + pair_idx[r];
        uint2 hv = __ldg(&full2[row * 32 + lane]);
        const __half2* hp = reinterpret_cast<const __half2*>(&hv);
        float2 f0 = __half22float2(hp[0]);
        float2 f1 = __half22float2(hp[1]);
        float4 s;
        s.x = f0.x; s.y = f0.y; s.z = f1.x; s.w = f1.y;
        out[(size_t)r * 32 + lane] = s;
    }
}

extern "C" void kernel_launch(void* const* d_in, const int* in_sizes, int n_in,
                              void* d_out, int out_size) {
    const float* level_tab    = (const float*)d_in[0];
    const float* type_tab     = (const float*)d_in[1];
    const float* feature_tab  = (const float*)d_in[2];
    const float* exchange_tab = (const float*)d_in[3];
    const float* pair_tab     = (const float*)d_in[4];
    const float* W            = (const float*)d_in[5];
    const float* b            = (const float*)d_in[6];
    const int* level_idx      = (const int*)d_in[7];
    const int* type_idx       = (const int*)d_in[8];
    const int* feature_idx    = (const int*)d_in[9];
    const int* exchange_idx   = (const int*)d_in[10];
    const int* pair_idx       = (const int*)d_in[11];

    int n = in_sizes[7];   // N rows

    int sm_count = 148;
    cudaDeviceGetAttribute(&sm_count, cudaDevAttrMultiProcessorCount, 0);

    // 1280 independent warp-tasks over 4864 warps -> one pass, all parallel.
    base_kernel<<<4 * sm_count, 256>>>(level_tab, type_tab, feature_tab,
                                       exchange_tab, pair_tab, W, b);
    expand_kernel<<<4 * sm_count, 256>>>();

    // 6 blocks/SM x 256 threads = 48 warps/SM, no smem
    gather_kernel<<<6 * sm_count, 256>>>(level_idx, type_idx, feature_idx,
                                         exchange_idx, pair_idx,
                                         (float4*)d_out, n);
}